// round 1
// baseline (speedup 1.0000x reference)
#include <cuda_runtime.h>
#include <math.h>

#define NSNR 2048
#define NT   4096
#define NP   100
#define NI   99
#define TPB  256
#define VPT  (NT / TPB)   // 16
#define NWARP (TPB / 32)

// ---------------------------------------------------------------------------
// Scratch (no cudaMalloc allowed): spline coeffs per row (a,b,c,d planes of
// 100 each, 99 used) and per-row partial results.
// ---------------------------------------------------------------------------
__device__ float g_coef[NSNR][400];
__device__ float g_rowsum[NSNR];

// Precomputed Thomas forward-elimination multipliers for the constant
// tridiagonal matrix tri(1,4,1) of size 98: cp[0]=1/4, cp[i]=1/(4-cp[i-1]).
struct CpTab { float v[98]; };
static constexpr CpTab make_cp() {
    CpTab t{};
    double c = 0.25;
    t.v[0] = (float)c;
    for (int i = 1; i < 98; i++) { c = 1.0 / (4.0 - c); t.v[i] = (float)c; }
    return t;
}
__constant__ CpTab d_cp = make_cp();

// ---------------------------------------------------------------------------
// Block-wide exclusive scan of one float per thread. Returns exclusive prefix;
// *total gets the block-wide inclusive total. Contains __syncthreads.
// ---------------------------------------------------------------------------
__device__ __forceinline__ float block_scan_excl(float v, float* warp_sums, float* total) {
    int lane = threadIdx.x & 31, wid = threadIdx.x >> 5;
    float x = v;
#pragma unroll
    for (int o = 1; o < 32; o <<= 1) {
        float y = __shfl_up_sync(0xffffffffu, x, o);
        if (lane >= o) x += y;
    }
    if (lane == 31) warp_sums[wid] = x;
    __syncthreads();
    if (wid == 0) {
        float w = (lane < NWARP) ? warp_sums[lane] : 0.0f;
#pragma unroll
        for (int o = 1; o < NWARP; o <<= 1) {
            float y = __shfl_up_sync(0xffffffffu, w, o);
            if (lane >= o) w += y;
        }
        if (lane < NWARP) warp_sums[lane] = w;
    }
    __syncthreads();
    float excl = (x - v) + (wid ? warp_sums[wid - 1] : 0.0f);
    *total = warp_sums[NWARP - 1];
    return excl;
}

// ---------------------------------------------------------------------------
// Kernel 1: per row of obs_data -> quantile function Q (100 pts) -> natural
// cubic spline coefficients written to g_coef[row].
// ---------------------------------------------------------------------------
__global__ void __launch_bounds__(TPB) quantile_spline_kernel(
    const float* __restrict__ obs, const float* __restrict__ t)
{
    __shared__ float sc[NT];        // cumulative trapezoid of |obs| (unnormalized CDF)
    __shared__ float sQ[NP];        // quantile values
    __shared__ float sM[NP];        // spline second derivatives
    __shared__ float sdp[98];       // Thomas forward pass
    __shared__ float warp_sums[NWARP];

    const int row = blockIdx.x;
    const float* __restrict__ y = obs + (size_t)row * NT;
    const float dt = t[1] - t[0];

    // --- trapezoid-increment scan ---
    const int base = threadIdx.x * VPT;
    float prev = (base == 0) ? 0.0f : fabsf(y[base - 1]);
    float loc[VPT];
    float run = 0.0f;
#pragma unroll
    for (int k = 0; k < VPT; k++) {
        float cur = fabsf(y[base + k]);
        float e = (base + k == 0) ? 0.0f : 0.5f * dt * (cur + prev);
        run += e;
        loc[k] = run;
        prev = cur;
    }
    float total;
    float excl = block_scan_excl(run, warp_sums, &total);
#pragma unroll
    for (int k = 0; k < VPT; k++) sc[base + k] = loc[k] + excl;
    __syncthreads();

    // --- inverse CDF at 100 quantiles: find j with S[j] <= p*T < S[j+1] ---
    if (threadIdx.x < NP) {
        int k = threadIdx.x;
        float p = (float)k / 99.0f;                 // exact 1.0 at endpoint
        float target = p * total;
        int lo = 0, hi = NT - 1;
        while (lo < hi) {
            int mid = (lo + hi + 1) >> 1;
            if (sc[mid] <= target) lo = mid; else hi = mid - 1;
        }
        int j = min(lo, NT - 2);
        float den = sc[j + 1] - sc[j];
        float q = (float)j * dt;
        if (den > 0.0f) q += (target - sc[j]) * dt / den;
        sQ[k] = q;
    }
    __syncthreads();

    // --- Thomas solve of tri(1,4,1) * M_int = rhs (size 98), cp precomputed ---
    if (threadIdx.x == 0) {
        const float HH = (float)((1.0 / 99.0) * (1.0 / 99.0));   // h*h
        float dp_prev = 0.0f;
        for (int i = 0; i < 98; i++) {
            float rhs = 6.0f * (sQ[i + 2] - 2.0f * sQ[i + 1] + sQ[i]) / HH;
            float dp = (rhs - dp_prev) * d_cp.v[i];
            sdp[i] = dp;
            dp_prev = dp;
        }
        sM[0] = 0.0f;
        sM[NP - 1] = 0.0f;
        float mnext = sdp[97];
        sM[98] = mnext;
        for (int i = 96; i >= 0; i--) {
            mnext = sdp[i] - d_cp.v[i] * mnext;
            sM[i + 1] = mnext;
        }
    }
    __syncthreads();

    // --- spline coefficients (99 intervals), parallel across threads ---
    if (threadIdx.x < NI) {
        int i = threadIdx.x;
        const float H = (float)(1.0 / 99.0);
        float Mi = sM[i], Mi1 = sM[i + 1];
        float a = sQ[i];
        float b = (sQ[i + 1] - sQ[i]) / H - H * (2.0f * Mi + Mi1) / 6.0f;
        float c = Mi * 0.5f;
        float d = (Mi1 - Mi) / (6.0f * H);
        float* cf = g_coef[row];
        cf[i]       = a;
        cf[100 + i] = b;
        cf[200 + i] = c;
        cf[300 + i] = d;
    }
}

// ---------------------------------------------------------------------------
// Kernel 2: per row of f -> normalized CDF F_j on the fly (no smem array),
// spline eval at F_j, trapezoid of diff^2 * f_tilde -> g_rowsum[row].
// ---------------------------------------------------------------------------
__global__ void __launch_bounds__(TPB) loss_kernel(
    const float* __restrict__ f, const float* __restrict__ t)
{
    __shared__ float scf[400];        // a/b/c/d planes
    __shared__ float warp_sums[NWARP];
    __shared__ float red[NWARP];
    __shared__ float sends[2];        // g at j=0 and j=NT-1

    const int row = blockIdx.x;
    const float* __restrict__ y = f + (size_t)row * NT;
    const float dt = t[1] - t[0];

    for (int i = threadIdx.x; i < 400; i += TPB) scf[i] = g_coef[row][i];

    const int base = threadIdx.x * VPT;
    float prev = (base == 0) ? 0.0f : fabsf(y[base - 1]);
    float loc[VPT], absv[VPT];
    float run = 0.0f;
#pragma unroll
    for (int k = 0; k < VPT; k++) {
        float cur = fabsf(y[base + k]);
        absv[k] = cur;
        float e = (base + k == 0) ? 0.0f : 0.5f * dt * (cur + prev);
        run += e;
        loc[k] = run;
        prev = cur;
    }
    float total;
    float excl = block_scan_excl(run, warp_sums, &total);   // syncs: scf now visible

    const float invT = 1.0f / total;
    const float H = (float)(1.0 / 99.0);
    float gsum = 0.0f;
#pragma unroll
    for (int k = 0; k < VPT; k++) {
        int j = base + k;
        float F = (loc[k] + excl) * invT;
        float xi = fminf(fmaxf(F, 0.0f), 1.0f);
        int idx = (int)(xi / H);
        idx = min(max(idx, 0), NI - 1);
        float dx = xi - (float)idx * H;
        float a = scf[idx], b = scf[100 + idx], c = scf[200 + idx], d = scf[300 + idx];
        float val = a + dx * (b + dx * (c + dx * d));
        float tj = (float)j * dt;
        float diff = tj - val;
        float w = absv[k] * invT;
        float g = diff * diff * w;
        gsum += g;
        if (j == 0) sends[0] = g;
        if (j == NT - 1) sends[1] = g;
    }

    // block reduce
#pragma unroll
    for (int o = 16; o; o >>= 1) gsum += __shfl_down_sync(0xffffffffu, gsum, o);
    if ((threadIdx.x & 31) == 0) red[threadIdx.x >> 5] = gsum;
    __syncthreads();
    if (threadIdx.x == 0) {
        float s = 0.0f;
#pragma unroll
        for (int w = 0; w < NWARP; w++) s += red[w];
        g_rowsum[row] = dt * (s - 0.5f * (sends[0] + sends[1]));
    }
}

// ---------------------------------------------------------------------------
// Kernel 3: deterministic double-precision reduction of 2048 row sums.
// ---------------------------------------------------------------------------
__global__ void __launch_bounds__(TPB) reduce_kernel(float* __restrict__ out)
{
    __shared__ double red[NWARP];
    double s = 0.0;
    for (int i = threadIdx.x; i < NSNR; i += TPB) s += (double)g_rowsum[i];
#pragma unroll
    for (int o = 16; o; o >>= 1) s += __shfl_down_sync(0xffffffffu, s, o);
    if ((threadIdx.x & 31) == 0) red[threadIdx.x >> 5] = s;
    __syncthreads();
    if (threadIdx.x == 0) {
        double tot = 0.0;
#pragma unroll
        for (int w = 0; w < NWARP; w++) tot += red[w];
        out[0] = (float)tot;
    }
}

// ---------------------------------------------------------------------------
extern "C" void kernel_launch(void* const* d_in, const int* in_sizes, int n_in,
                              void* d_out, int out_size)
{
    const float* f   = (const float*)d_in[0];
    const float* obs = (const float*)d_in[1];
    const float* t   = (const float*)d_in[2];

    quantile_spline_kernel<<<NSNR, TPB>>>(obs, t);
    loss_kernel<<<NSNR, TPB>>>(f, t);
    reduce_kernel<<<1, TPB>>>((float*)d_out);
}

// round 2
// speedup vs baseline: 1.2607x; 1.2607x over previous
#include <cuda_runtime.h>
#include <math.h>

#define NSNR 2048
#define NT   4096
#define NP   100
#define NI   99
#define TPB  256
#define VPT  (NT / TPB)   // 16
#define NWARP (TPB / 32)
#define PAD(i) ((i) + ((i) >> 5))

__device__ float g_rowsum[NSNR];

// Precomputed Thomas forward-elimination multipliers for tri(1,4,1), n=98.
struct CpTab { float v[98]; };
static constexpr CpTab make_cp() {
    CpTab t{};
    double c = 0.25;
    t.v[0] = (float)c;
    for (int i = 1; i < 98; i++) { c = 1.0 / (4.0 - c); t.v[i] = (float)c; }
    return t;
}
__constant__ CpTab d_cp = make_cp();

// Block-wide exclusive scan of one float per thread. Contains __syncthreads.
__device__ __forceinline__ float block_scan_excl(float v, float* warp_sums, float* total) {
    int lane = threadIdx.x & 31, wid = threadIdx.x >> 5;
    float x = v;
#pragma unroll
    for (int o = 1; o < 32; o <<= 1) {
        float y = __shfl_up_sync(0xffffffffu, x, o);
        if (lane >= o) x += y;
    }
    if (lane == 31) warp_sums[wid] = x;
    __syncthreads();
    if (wid == 0) {
        float w = (lane < NWARP) ? warp_sums[lane] : 0.0f;
#pragma unroll
        for (int o = 1; o < NWARP; o <<= 1) {
            float y = __shfl_up_sync(0xffffffffu, w, o);
            if (lane >= o) w += y;
        }
        if (lane < NWARP) warp_sums[lane] = w;
    }
    __syncthreads();
    float excl = (x - v) + (wid ? warp_sums[wid - 1] : 0.0f);
    *total = warp_sums[NWARP - 1];
    return excl;
}

// Coalesced float4 load of |src row| into padded smem. No sync inside.
__device__ __forceinline__ void load_abs_padded(const float* __restrict__ src, float* sv) {
    const float4* __restrict__ s4 = reinterpret_cast<const float4*>(src);
#pragma unroll
    for (int i = 0; i < 4; i++) {
        int j = threadIdx.x + TPB * i;          // float4 index, coalesced
        float4 v = s4[j];
        int e = 4 * j;
        sv[PAD(e + 0)] = fabsf(v.x);
        sv[PAD(e + 1)] = fabsf(v.y);
        sv[PAD(e + 2)] = fabsf(v.z);
        sv[PAD(e + 3)] = fabsf(v.w);
    }
}

// ---------------------------------------------------------------------------
// Fused kernel: per row, (A) obs -> CDF -> quantiles -> spline coeffs in smem,
// (B) f -> CDF -> spline eval -> weighted trapezoid -> g_rowsum[row].
// ---------------------------------------------------------------------------
__global__ void __launch_bounds__(TPB) wasserstein_kernel(
    const float* __restrict__ f, const float* __restrict__ obs,
    const float* __restrict__ t)
{
    __shared__ float sv[NT + (NT >> 5)];   // padded data / CDF buffer (16.9 KB)
    __shared__ float sQ[NP];
    __shared__ float sM[NP];
    __shared__ float sdp[98];
    __shared__ float scf[400];             // spline coeff planes a/b/c/d
    __shared__ float warp_sums[NWARP];
    __shared__ float red[NWARP];

    const int row = blockIdx.x;
    const float dt = t[1] - t[0];
    const int base = threadIdx.x * VPT;

    // ================= Phase A: obs -> spline coefficients =================
    load_abs_padded(obs + (size_t)row * NT, sv);
    __syncthreads();

    float loc[VPT];
    {
        float prev = (base == 0) ? 0.0f : sv[PAD(base - 1)];
        float run = 0.0f;
#pragma unroll
        for (int k = 0; k < VPT; k++) {
            float cur = sv[PAD(base + k)];
            float e = (base + k == 0) ? 0.0f : 0.5f * dt * (cur + prev);
            run += e;
            loc[k] = run;
            prev = cur;
        }
        float total;
        float excl = block_scan_excl(run, warp_sums, &total);  // has syncs
#pragma unroll
        for (int k = 0; k < VPT; k++) sv[PAD(base + k)] = loc[k] + excl;
        if (threadIdx.x == 0) warp_sums[0] = total;  // keep total (scan reuses buf)
        __syncthreads();

        // inverse CDF at 100 quantiles
        float T = warp_sums[0];
        if (threadIdx.x < NP) {
            int k = threadIdx.x;
            float p = (float)k / 99.0f;
            float target = p * T;
            int lo = 0, hi = NT - 1;
            while (lo < hi) {
                int mid = (lo + hi + 1) >> 1;
                if (sv[PAD(mid)] <= target) lo = mid; else hi = mid - 1;
            }
            int j = min(lo, NT - 2);
            float den = sv[PAD(j + 1)] - sv[PAD(j)];
            float q = (float)j * dt;
            if (den > 0.0f) q += (target - sv[PAD(j)]) * dt / den;
            sQ[k] = q;
        }
    }
    __syncthreads();

    // Thomas solve of tri(1,4,1)*M_int = rhs (n=98), cp precomputed
    if (threadIdx.x == 0) {
        const float HH = (float)((1.0 / 99.0) * (1.0 / 99.0));
        float dp_prev = 0.0f;
        for (int i = 0; i < 98; i++) {
            float rhs = 6.0f * (sQ[i + 2] - 2.0f * sQ[i + 1] + sQ[i]) / HH;
            float dp = (rhs - dp_prev) * d_cp.v[i];
            sdp[i] = dp;
            dp_prev = dp;
        }
        sM[0] = 0.0f;
        sM[NP - 1] = 0.0f;
        float mnext = sdp[97];
        sM[98] = mnext;
        for (int i = 96; i >= 0; i--) {
            mnext = sdp[i] - d_cp.v[i] * mnext;
            sM[i + 1] = mnext;
        }
    }
    __syncthreads();

    if (threadIdx.x < NI) {
        int i = threadIdx.x;
        const float H = (float)(1.0 / 99.0);
        float Mi = sM[i], Mi1 = sM[i + 1];
        scf[i]       = sQ[i];
        scf[100 + i] = (sQ[i + 1] - sQ[i]) / H - H * (2.0f * Mi + Mi1) / 6.0f;
        scf[200 + i] = Mi * 0.5f;
        scf[300 + i] = (Mi1 - Mi) / (6.0f * H);
    }
    __syncthreads();

    // ================= Phase B: f -> loss contribution =================
    load_abs_padded(f + (size_t)row * NT, sv);
    __syncthreads();

    float prev = (base == 0) ? 0.0f : sv[PAD(base - 1)];
    float run = 0.0f;
#pragma unroll
    for (int k = 0; k < VPT; k++) {
        float cur = sv[PAD(base + k)];
        float e = (base + k == 0) ? 0.0f : 0.5f * dt * (cur + prev);
        run += e;
        loc[k] = run;
        prev = cur;
    }
    float total;
    float excl = block_scan_excl(run, warp_sums, &total);

    const float invT = 1.0f / total;
    const float H = (float)(1.0 / 99.0);
    float gsum = 0.0f;
#pragma unroll
    for (int k = 0; k < VPT; k++) {
        int j = base + k;
        float F = (loc[k] + excl) * invT;
        float xi = fminf(fmaxf(F, 0.0f), 1.0f);
        int idx = min((int)(xi / H), NI - 1);
        float dx = xi - (float)idx * H;
        float a = scf[idx], b = scf[100 + idx], c = scf[200 + idx], d = scf[300 + idx];
        float val = a + dx * (b + dx * (c + dx * d));
        float tj = (float)j * dt;
        float diff = tj - val;
        float w = sv[PAD(j)] * invT;     // re-read |f| from smem (saves 16 regs)
        float g = diff * diff * w;
        gsum += g;
        if (j == 0 || j == NT - 1) gsum -= 0.5f * g;   // trapezoid edge terms
    }

#pragma unroll
    for (int o = 16; o; o >>= 1) gsum += __shfl_down_sync(0xffffffffu, gsum, o);
    if ((threadIdx.x & 31) == 0) red[threadIdx.x >> 5] = gsum;
    __syncthreads();
    if (threadIdx.x == 0) {
        float s = 0.0f;
#pragma unroll
        for (int w = 0; w < NWARP; w++) s += red[w];
        g_rowsum[row] = dt * s;
    }
}

// ---------------------------------------------------------------------------
// Deterministic double-precision reduction of 2048 row sums -> scalar.
// ---------------------------------------------------------------------------
__global__ void __launch_bounds__(TPB) reduce_kernel(float* __restrict__ out)
{
    __shared__ double red[NWARP];
    double s = 0.0;
    for (int i = threadIdx.x; i < NSNR; i += TPB) s += (double)g_rowsum[i];
#pragma unroll
    for (int o = 16; o; o >>= 1) s += __shfl_down_sync(0xffffffffu, s, o);
    if ((threadIdx.x & 31) == 0) red[threadIdx.x >> 5] = s;
    __syncthreads();
    if (threadIdx.x == 0) {
        double tot = 0.0;
#pragma unroll
        for (int w = 0; w < NWARP; w++) tot += red[w];
        out[0] = (float)tot;
    }
}

// ---------------------------------------------------------------------------
extern "C" void kernel_launch(void* const* d_in, const int* in_sizes, int n_in,
                              void* d_out, int out_size)
{
    const float* f   = (const float*)d_in[0];
    const float* obs = (const float*)d_in[1];
    const float* t   = (const float*)d_in[2];

    wasserstein_kernel<<<NSNR, TPB>>>(f, obs, t);
    reduce_kernel<<<1, TPB>>>((float*)d_out);
}

// round 3
// speedup vs baseline: 1.9506x; 1.5472x over previous
#include <cuda_runtime.h>
#include <math.h>
#include <stdint.h>

#define NSNR 2048
#define NT   4096
#define NP   100
#define NI   99
#define TPB  256
#define VPT  (NT / TPB)   // 16
#define NWARP (TPB / 32)
#define PAD(i) ((i) + ((i) >> 5))

__device__ double       g_acc;     // zero-init; reset by last block each run
__device__ unsigned int g_ticket;  // self-resetting via atomicInc wrap

// Precomputed Thomas forward-elimination multipliers for tri(1,4,1), n=98.
struct CpTab { float v[98]; };
static constexpr CpTab make_cp() {
    CpTab t{};
    double c = 0.25;
    t.v[0] = (float)c;
    for (int i = 1; i < 98; i++) { c = 1.0 / (4.0 - c); t.v[i] = (float)c; }
    return t;
}
__constant__ CpTab d_cp = make_cp();

// ---------------------------------------------------------------------------
__device__ __forceinline__ uint32_t smem_u32(const void* p) {
    return (uint32_t)__cvta_generic_to_shared(p);
}
__device__ __forceinline__ void cp_async16(uint32_t saddr, const void* gptr) {
    asm volatile("cp.async.cg.shared.global [%0], [%1], 16;" :: "r"(saddr), "l"(gptr));
}
__device__ __forceinline__ void cp_commit() {
    asm volatile("cp.async.commit_group;");
}
template <int N> __device__ __forceinline__ void cp_wait() {
    asm volatile("cp.async.wait_group %0;" :: "n"(N));
}

// Block-wide exclusive scan of one float per thread. Contains __syncthreads.
__device__ __forceinline__ float block_scan_excl(float v, float* warp_sums, float* total) {
    int lane = threadIdx.x & 31, wid = threadIdx.x >> 5;
    float x = v;
#pragma unroll
    for (int o = 1; o < 32; o <<= 1) {
        float y = __shfl_up_sync(0xffffffffu, x, o);
        if (lane >= o) x += y;
    }
    if (lane == 31) warp_sums[wid] = x;
    __syncthreads();
    if (wid == 0) {
        float w = (lane < NWARP) ? warp_sums[lane] : 0.0f;
#pragma unroll
        for (int o = 1; o < NWARP; o <<= 1) {
            float y = __shfl_up_sync(0xffffffffu, w, o);
            if (lane >= o) w += y;
        }
        if (lane < NWARP) warp_sums[lane] = w;
    }
    __syncthreads();
    float excl = (x - v) + (wid ? warp_sums[wid - 1] : 0.0f);
    *total = warp_sums[NWARP - 1];
    return excl;
}

// ---------------------------------------------------------------------------
// Fully fused: obs -> spline; f -> loss; global reduction via atomics.
// ---------------------------------------------------------------------------
__global__ void __launch_bounds__(TPB, 6) wasserstein_kernel(
    const float* __restrict__ f, const float* __restrict__ obs,
    const float* __restrict__ t, float* __restrict__ out)
{
    // svA: raw obs (striped float4) then overwritten by padded CDF
    __shared__ float  svA[NT + (NT >> 5)];
    __shared__ float4 svF4[NT / 4];          // raw f row
    __shared__ float4 scf4[NP];              // spline coeffs (a,b,c,d)
    __shared__ float  sQ[NP];
    __shared__ float  sM[NP];
    __shared__ float  sdp[98];
    __shared__ float  warp_sums[NWARP];
    __shared__ float  red[NWARP];
    __shared__ float  sTot;

    const int   row  = blockIdx.x;
    const float dt   = t[1] - t[0];
    const int   base = threadIdx.x * VPT;

    // ---- issue ALL DRAM traffic for this block up front (cp.async) ----
    {
        const float4* go = reinterpret_cast<const float4*>(obs + (size_t)row * NT);
        const float4* gf = reinterpret_cast<const float4*>(f   + (size_t)row * NT);
        uint32_t sa = smem_u32(svA);
        uint32_t sf = smem_u32(svF4);
#pragma unroll
        for (int i = 0; i < 4; i++) {
            int j = threadIdx.x + TPB * i;
            cp_async16(sa + 16u * j, go + j);
        }
        cp_commit();
#pragma unroll
        for (int i = 0; i < 4; i++) {
            int j = threadIdx.x + TPB * i;
            cp_async16(sf + 16u * j, gf + j);
        }
        cp_commit();
    }

    // ================= Phase A: obs -> spline coefficients =================
    cp_wait<1>();          // obs chunks (own thread) done
    __syncthreads();       // everyone's obs chunks visible

    float absv[VPT];
    {
        const float4* ra = reinterpret_cast<const float4*>(svA);
#pragma unroll
        for (int q = 0; q < VPT / 4; q++) {
            float4 v = ra[base / 4 + q];
            absv[4 * q + 0] = fabsf(v.x);
            absv[4 * q + 1] = fabsf(v.y);
            absv[4 * q + 2] = fabsf(v.z);
            absv[4 * q + 3] = fabsf(v.w);
        }
    }
    float prev = (base == 0) ? 0.0f : fabsf(svA[base - 1]);

    float run = 0.0f;
    {
        float p = prev;
#pragma unroll
        for (int k = 0; k < VPT; k++) {
            float cur = absv[k];
            float e = (base + k == 0) ? 0.0f : 0.5f * dt * (cur + p);
            run += e;
            p = cur;
        }
    }
    float total;
    float excl = block_scan_excl(run, warp_sums, &total);   // syncs: raw reads done

    // overwrite svA with padded CDF
    {
        float p = prev, r2 = 0.0f;
#pragma unroll
        for (int k = 0; k < VPT; k++) {
            float cur = absv[k];
            float e = (base + k == 0) ? 0.0f : 0.5f * dt * (cur + p);
            r2 += e;
            svA[PAD(base + k)] = r2 + excl;
            p = cur;
        }
    }
    if (threadIdx.x == 0) sTot = total;
    __syncthreads();

    // inverse CDF at 100 quantiles
    if (threadIdx.x < NP) {
        int k = threadIdx.x;
        float p = (float)k / 99.0f;
        float target = p * sTot;
        int lo = 0, hi = NT - 1;
        while (lo < hi) {
            int mid = (lo + hi + 1) >> 1;
            if (svA[PAD(mid)] <= target) lo = mid; else hi = mid - 1;
        }
        int j = min(lo, NT - 2);
        float den = svA[PAD(j + 1)] - svA[PAD(j)];
        float q = (float)j * dt;
        if (den > 0.0f) q += (target - svA[PAD(j)]) * dt / den;
        sQ[k] = q;
    }
    __syncthreads();

    // u_i = rhs_i * cp_i computed in parallel (98 threads)
    if (threadIdx.x < 98) {
        int i = threadIdx.x;
        const float S = 6.0f * 9801.0f;   // 6 / h^2
        float rhs = S * (sQ[i + 2] - 2.0f * sQ[i + 1] + sQ[i]);
        sdp[i] = rhs * d_cp.v[i];
    }
    __syncthreads();

    // serial recurrences (single FFMA chains)
    if (threadIdx.x == 0) {
        float dp = sdp[0];
        sdp[0] = dp;
#pragma unroll 7
        for (int i = 1; i < 98; i++) {
            dp = fmaf(-d_cp.v[i], dp, sdp[i]);
            sdp[i] = dp;
        }
        sM[0] = 0.0f;
        sM[NP - 1] = 0.0f;
        float mnext = sdp[97];
        sM[98] = mnext;
#pragma unroll 7
        for (int i = 96; i >= 0; i--) {
            mnext = fmaf(-d_cp.v[i], mnext, sdp[i]);
            sM[i + 1] = mnext;
        }
    }
    __syncthreads();

    if (threadIdx.x < NI) {
        int i = threadIdx.x;
        const float H    = (float)(1.0 / 99.0);
        const float invH = 99.0f;
        float Mi = sM[i], Mi1 = sM[i + 1];
        float4 c;
        c.x = sQ[i];
        c.y = (sQ[i + 1] - sQ[i]) * invH - H * (2.0f * Mi + Mi1) * (1.0f / 6.0f);
        c.z = Mi * 0.5f;
        c.w = (Mi1 - Mi) * (invH / 6.0f);
        scf4[i] = c;
    }
    __syncthreads();

    // ================= Phase B: f -> loss contribution =================
    cp_wait<0>();
    __syncthreads();

#pragma unroll
    for (int q = 0; q < VPT / 4; q++) {
        float4 v = svF4[base / 4 + q];
        absv[4 * q + 0] = fabsf(v.x);
        absv[4 * q + 1] = fabsf(v.y);
        absv[4 * q + 2] = fabsf(v.z);
        absv[4 * q + 3] = fabsf(v.w);
    }
    prev = (base == 0) ? 0.0f
                       : fabsf(reinterpret_cast<const float*>(svF4)[base - 1]);

    run = 0.0f;
    {
        float p = prev;
#pragma unroll
        for (int k = 0; k < VPT; k++) {
            float cur = absv[k];
            float e = (base + k == 0) ? 0.0f : 0.5f * dt * (cur + p);
            run += e;
            p = cur;
        }
    }
    excl = block_scan_excl(run, warp_sums, &total);

    const float invT = 1.0f / total;
    float gsum = 0.0f;
    {
        float p = prev, r2 = 0.0f;
#pragma unroll
        for (int k = 0; k < VPT; k++) {
            int j = base + k;
            float cur = absv[k];
            float e = (j == 0) ? 0.0f : 0.5f * dt * (cur + p);
            r2 += e;
            p = cur;

            float F  = (r2 + excl) * invT;
            float xi = fminf(fmaxf(F, 0.0f), 1.0f);
            int idx  = min((int)(xi * 99.0f), NI - 1);
            float dx = xi - (float)idx * (float)(1.0 / 99.0);
            float4 cf = scf4[idx];
            float val = cf.x + dx * (cf.y + dx * (cf.z + dx * cf.w));
            float tj  = (float)j * dt;
            float diff = tj - val;
            float g = diff * diff * (cur * invT);
            gsum += g;
            if (j == 0 || j == NT - 1) gsum -= 0.5f * g;   // trapezoid edges
        }
    }

#pragma unroll
    for (int o = 16; o; o >>= 1) gsum += __shfl_down_sync(0xffffffffu, gsum, o);
    if ((threadIdx.x & 31) == 0) red[threadIdx.x >> 5] = gsum;
    __syncthreads();

    if (threadIdx.x == 0) {
        float s = 0.0f;
#pragma unroll
        for (int w = 0; w < NWARP; w++) s += red[w];
        double my = (double)(dt * s);
        atomicAdd(&g_acc, my);
        __threadfence();
        unsigned tk = atomicInc(&g_ticket, NSNR - 1);   // wraps to 0 automatically
        if (tk == NSNR - 1) {
            out[0] = (float)g_acc;
            g_acc = 0.0;                                 // reset for next replay
        }
    }
}

// ---------------------------------------------------------------------------
extern "C" void kernel_launch(void* const* d_in, const int* in_sizes, int n_in,
                              void* d_out, int out_size)
{
    const float* f   = (const float*)d_in[0];
    const float* obs = (const float*)d_in[1];
    const float* t   = (const float*)d_in[2];

    wasserstein_kernel<<<NSNR, TPB>>>(f, obs, t, (float*)d_out);
}